// round 14
// baseline (speedup 1.0000x reference)
#include <cuda_runtime.h>
#include <cuda_bf16.h>

#define BATCH 64
#define NTOK  4096
#define CH    512
#define NUM_KEEP 2458            // ceil(4096 * 0.6)
#define TAIL (NTOK - NUM_KEEP)   // 1638
#define C4   (CH / 4)            // 128 float4 per token row
#define NGROUP 32                // tail groups per batch
#define TAIL_CTAS (BATCH * 8)    // 512 CTAs, 4 groups of 128 lanes each
#define COPY_CTAS 4916           // sel float4s / 4096 per CTA, exact
#define CHUNK 512                // elements per sorter CTA (8 chunks/batch)
#define NCHUNK 8

typedef unsigned long long u64;

// scratch (device globals; g_sum_tmp re-zeroed by kernel A every launch,
// everything else fully overwritten -> graph replays are deterministic)
__device__ u64    g_keys[BATCH * NTOK];      // 2 MB, chunk-sorted descending
__device__ int    g_sorted_idx[BATCH * NTOK];
__device__ float  g_tailw[BATCH * TAIL];     // UN-normalized exp weights
__device__ float  g_sum_tmp[BATCH];          // tail softmax denominator

// ---------------------------------------------------------------------------
// helpers
// ---------------------------------------------------------------------------
__device__ __forceinline__ float decode_score(u64 kk) {
    unsigned u = (unsigned)(kk >> 32);
    return (u & 0x80000000u) ? __uint_as_float(u & 0x7FFFFFFFu)
                             : __uint_as_float(~u);
}

__device__ __forceinline__ void cmpswap(u64& a, u64& c, bool desc) {
    bool sw = desc ? (a < c) : (a > c);
    if (sw) { u64 t = a; a = c; c = t; }
}

// warp finish: levels jstart..2 via shfl (2 elems/thread layout), then j=1.
__device__ __forceinline__ void wfin2d(u64& r0, u64& r1,
                                       int base, int jstart, bool d) {
    for (int j = jstart; j >= 2; j >>= 1) {
        int L = j >> 1;
        bool keepmax = (((base & j) == 0) == d);
        u64 o0 = __shfl_xor_sync(0xFFFFFFFFu, r0, L);
        u64 o1 = __shfl_xor_sync(0xFFFFFFFFu, r1, L);
        r0 = keepmax ? (r0 > o0 ? r0 : o0) : (r0 < o0 ? r0 : o0);
        r1 = keepmax ? (r1 > o1 ? r1 : o1) : (r1 < o1 ? r1 : o1);
    }
    cmpswap(r0, r1, d);
}

// ---------------------------------------------------------------------------
// Kernel A: 8 CTAs/batch, 256 threads, 2 elems/thread: sort each 512-chunk
// DESCENDING (45 levels vs 55 for 1024-chunks). shfl covers j<=32; smem
// quad passes for j>=64. Also zeroes extra slice + per-batch softmax sum.
// ---------------------------------------------------------------------------
__global__ __launch_bounds__(256)
void ts_sort1_kernel(const float* __restrict__ ax,
                     const float* __restrict__ ay,
                     float* __restrict__ extra)
{
    __shared__ u64 key[CHUNK];   // 4 KB

    const int cta   = blockIdx.x;        // 0..511
    const int b     = cta >> 3;
    const int c     = cta & 7;
    const int tid   = threadIdx.x;
    const int base  = tid << 1;          // element e0 in chunk (0..510)
    const int gbase = (c << 9) + base;   // token index within batch

    if (tid < 64) extra[b * CH + (c << 6) + tid] = 0.0f;
    if (tid == 0 && c == 0) g_sum_tmp[b] = 0.0f;

    u64 r0, r1;
    {
        float2 x = *(const float2*)(ax + b * NTOK + gbase);
        float2 y = *(const float2*)(ay + b * NTOK + gbase);
        float s0 = x.x + y.x, s1 = x.y + y.y;
        unsigned u0 = __float_as_uint(s0);
        u0 = (u0 & 0x80000000u) ? ~u0 : (u0 | 0x80000000u);
        unsigned u1 = __float_as_uint(s1);
        u1 = (u1 & 0x80000000u) ? ~u1 : (u1 | 0x80000000u);
        r0 = ((u64)u0 << 32) | (unsigned)(~gbase);
        r1 = ((u64)u1 << 32) | (unsigned)(~(gbase + 1));
    }

    // k = 2..64 : registers + shuffles only (descending network)
    cmpswap(r0, r1, (base & 2) == 0);
    for (int k = 4; k <= 64; k <<= 1)
        wfin2d(r0, r1, base, k >> 1, ((base & k) == 0));

    // k = 128, 256, 512 : smem quad passes (j>=64), warp finish
    for (int k = 128; k <= CHUNK; k <<= 1) {
        *(ulonglong2*)&key[base] = make_ulonglong2(r0, r1);
        __syncthreads();
        int j = k >> 1;
        while (j >= 64) {
            int j2 = j >> 1;
            if (tid < 128) {
                int q = tid;
                int i = ((q & ~(j2 - 1)) << 2) | (q & (j2 - 1));
                bool d = ((i & k) == 0);
                u64 a0 = key[i];
                u64 a1 = key[i + j2];
                u64 a2 = key[i + 2 * j2];
                u64 a3 = key[i + 3 * j2];
                cmpswap(a0, a2, d);
                cmpswap(a1, a3, d);
                cmpswap(a0, a1, d);
                cmpswap(a2, a3, d);
                key[i]          = a0;
                key[i + j2]     = a1;
                key[i + 2 * j2] = a2;
                key[i + 3 * j2] = a3;
            }
            __syncthreads();
            j >>= 2;
        }
        ulonglong2 p = *(ulonglong2*)&key[base];
        r0 = p.x; r1 = p.y;
        wfin2d(r0, r1, base, j, ((base & k) == 0));   // j is 32 or 16 here
    }

    *(ulonglong2*)(g_keys + b * NTOK + gbase) = make_ulonglong2(r0, r1);

    // all of this CTA's global writes are issued -> allow dependent launch
    cudaTriggerProgrammaticLaunchCompletion();
}

// ---------------------------------------------------------------------------
// Kernel B: 8-way merge-by-rank. 8 CTAs/batch (512 total), 256 threads.
// Each CTA loads all 8 chunks (32 KB) and ranks its own chunk's 512
// elements: rank = chunk position + count_greater in the 7 other chunks
// (10 guarded binary-search steps each; lo in [0,512] = 513 outcomes).
// ---------------------------------------------------------------------------
__global__ __launch_bounds__(256)
void ts_merge_kernel(float* __restrict__ mask_out)
{
    __shared__ u64 D[NTOK];      // 32 KB
    __shared__ float red[8];

    const int cta = blockIdx.x;          // 0..511
    const int b   = cta >> 3;
    const int c   = cta & 7;
    const int tid = threadIdx.x;

    // wait for kernel A's writes (g_keys, g_sum_tmp zero) to be visible
    cudaGridDependencySynchronize();

    // load the whole batch's keys (2048 ulonglong2 / 256 threads = 8 each)
    {
        const ulonglong2* src = (const ulonglong2*)(g_keys + b * NTOK);
        ulonglong2* dst = (ulonglong2*)D;
        #pragma unroll
        for (int i = 0; i < 8; ++i)
            dst[tid + (i << 8)] = src[tid + (i << 8)];
    }
    __syncthreads();

    float lsum = 0.0f;

    #pragma unroll
    for (int m = 0; m < 2; ++m) {
        const int pos = (tid << 1) + m;          // position in own chunk
        const u64 e = D[(c << 9) + pos];

        int rank = pos;
        #pragma unroll
        for (int oc = 0; oc < NCHUNK; ++oc) {
            if (oc == c) continue;
            const u64* __restrict__ A = D + (oc << 9);
            int lo = 0, hi = CHUNK;
            #pragma unroll
            for (int it = 0; it < 10; ++it) {    // 10 steps for 513 outcomes
                if (lo < hi) {
                    int mid = (lo + hi) >> 1;
                    if (A[mid] > e) lo = mid + 1; else hi = mid;
                }
            }
            rank += lo;                          // # elements > e in A
        }

        const int idx = (int)(~(unsigned)e);
        g_sorted_idx[b * NTOK + rank] = idx;
        mask_out[b * NTOK + idx] = (rank < NUM_KEEP) ? 1.0f : 0.0f;
        if (rank >= NUM_KEEP) {
            float w = expf(decode_score(e));     // unnormalized; fp32-safe
            g_tailw[b * TAIL + (rank - NUM_KEEP)] = w;
            lsum += w;
        }
    }

    // block-reduce lsum, one atomicAdd per CTA into the batch denominator
    for (int off = 16; off > 0; off >>= 1)
        lsum += __shfl_down_sync(0xFFFFFFFFu, lsum, off);
    if ((tid & 31) == 0) red[tid >> 5] = lsum;
    __syncthreads();
    if (tid < 8) {
        float v = red[tid];
        for (int off = 4; off > 0; off >>= 1)
            v += __shfl_down_sync(0x000000FFu, v, off);
        if (tid == 0) atomicAdd(&g_sum_tmp[b], v);
    }

    // all global writes issued -> allow main kernel to proceed
    cudaTriggerProgrammaticLaunchCompletion();
}

// ---------------------------------------------------------------------------
// MAIN kernel: tail accumulation + gather copy (byte-identical to R13).
// __launch_bounds__(512,4) caps regs at 32 -> 4 CTAs/SM; tail path
// pre-reduces its 4 sub-groups in smem before atomics.
// ---------------------------------------------------------------------------
__global__ __launch_bounds__(512, 4)
void ts_main_kernel(const float* __restrict__ tokens,
                    float* __restrict__ sel,
                    float* __restrict__ extra)
{
    __shared__ float4 part[3][128];   // 6 KB, tail path only

    if (blockIdx.x < TAIL_CTAS) {
        const int b    = blockIdx.x >> 3;
        const int sub  = threadIdx.x >> 7;                   // 0..3
        const int g    = ((blockIdx.x & 7) << 2) | sub;      // 0..31
        const int lane = threadIdx.x & 127;

        const int* __restrict__ sidx = g_sorted_idx + b * NTOK + NUM_KEEP;
        const float* __restrict__ w  = g_tailw + b * TAIL;
        const float4* __restrict__ tok4 = (const float4*)tokens
                                          + ((long long)b * NTOK << 7);

        cudaGridDependencySynchronize();   // wait for merge results

        float4 acc = make_float4(0.f, 0.f, 0.f, 0.f);
        int r = g;
        for (; r + NGROUP < TAIL; r += 2 * NGROUP) {
            int   i0 = sidx[r],    i1 = sidx[r + NGROUP];
            float w0 = w[r],       w1 = w[r + NGROUP];
            float4 v0 = __ldcs(&tok4[((long long)i0 << 7) + lane]);
            float4 v1 = __ldcs(&tok4[((long long)i1 << 7) + lane]);
            acc.x += w0 * v0.x + w1 * v1.x;
            acc.y += w0 * v0.y + w1 * v1.y;
            acc.z += w0 * v0.z + w1 * v1.z;
            acc.w += w0 * v0.w + w1 * v1.w;
        }
        if (r < TAIL) {
            int i0 = sidx[r];
            float w0 = w[r];
            float4 v0 = __ldcs(&tok4[((long long)i0 << 7) + lane]);
            acc.x += w0 * v0.x; acc.y += w0 * v0.y;
            acc.z += w0 * v0.z; acc.w += w0 * v0.w;
        }

        // intra-CTA reduction: sub-groups 1..3 -> smem, sub-group 0 finishes
        if (sub > 0) part[sub - 1][lane] = acc;
        __syncthreads();
        if (sub == 0) {
            #pragma unroll
            for (int i = 0; i < 3; ++i) {
                float4 p = part[i][lane];
                acc.x += p.x; acc.y += p.y; acc.z += p.z; acc.w += p.w;
            }
            float s = 1.0f / g_sum_tmp[b];
            float* dst = extra + b * CH + (lane << 2);
            atomicAdd(dst + 0, acc.x * s);
            atomicAdd(dst + 1, acc.y * s);
            atomicAdd(dst + 2, acc.z * s);
            atomicAdd(dst + 3, acc.w * s);
        }
    } else {
        const int cta = blockIdx.x - TAIL_CTAS;
        const int v0  = (cta << 12) + threadIdx.x;

        cudaGridDependencySynchronize();   // wait for merge results

        // two halves of 4 float4s: lower live-register footprint (32-reg cap)
        #pragma unroll
        for (int h = 0; h < 2; ++h) {
            long long srcoff[4];
            int vv[4];
            #pragma unroll
            for (int i = 0; i < 4; ++i) {
                int v = v0 + ((h * 4 + i) << 9);
                vv[i] = v;
                int row  = v >> 7;                 // b*NUM_KEEP + r
                int lane = v & 127;
                int b = row / NUM_KEEP;
                int r = row - b * NUM_KEEP;
                int idx = __ldg(&g_sorted_idx[b * NTOK + r]);
                srcoff[i] = (((long long)b * NTOK + idx) << 7) + lane;
            }
            float4 val[4];
            #pragma unroll
            for (int i = 0; i < 4; ++i)
                val[i] = __ldcs(((const float4*)tokens) + srcoff[i]);
            #pragma unroll
            for (int i = 0; i < 4; ++i)
                __stcs(((float4*)sel) + vv[i], val[i]);
        }
    }
}

// ---------------------------------------------------------------------------
extern "C" void kernel_launch(void* const* d_in, const int* in_sizes, int n_in,
                              void* d_out, int out_size)
{
    const float* tokens = (const float*)d_in[0];
    const float* ax     = (const float*)d_in[1];
    const float* ay     = (const float*)d_in[2];

    float* out = (float*)d_out;
    float* sel   = out;                                      // B*NUM_KEEP*C
    float* extra = out + (long long)BATCH * NUM_KEEP * CH;   // B*C
    float* mask  = extra + (long long)BATCH * CH;            // B*N

    // kernel A: plain launch
    ts_sort1_kernel<<<BATCH * NCHUNK, 256>>>(ax, ay, extra);

    // kernel B and MAIN: programmatic dependent launches
    cudaLaunchAttribute attr[1];
    attr[0].id = cudaLaunchAttributeProgrammaticStreamSerialization;
    attr[0].val.programmaticStreamSerializationAllowed = 1;

    {
        cudaLaunchConfig_t cfg = {};
        cfg.gridDim  = dim3(BATCH * NCHUNK);
        cfg.blockDim = dim3(256);
        cfg.attrs = attr;
        cfg.numAttrs = 1;
        cudaLaunchKernelEx(&cfg, ts_merge_kernel, mask);
    }
    {
        cudaLaunchConfig_t cfg = {};
        cfg.gridDim  = dim3(TAIL_CTAS + COPY_CTAS);
        cfg.blockDim = dim3(512);
        cfg.attrs = attr;
        cfg.numAttrs = 1;
        cudaLaunchKernelEx(&cfg, ts_main_kernel, tokens, sel, extra);
    }
}

// round 15
// speedup vs baseline: 1.1145x; 1.1145x over previous
#include <cuda_runtime.h>
#include <cuda_bf16.h>

#define BATCH 64
#define NTOK  4096
#define CH    512
#define NUM_KEEP 2458            // ceil(4096 * 0.6)
#define TAIL (NTOK - NUM_KEEP)   // 1638
#define C4   (CH / 4)            // 128 float4 per token row
#define NGROUP 32                // tail groups per batch
#define TAIL_CTAS (BATCH * 8)    // 512 CTAs, 4 groups of 128 lanes each
#define COPY_CTAS 4916           // sel float4s / 4096 per CTA, exact
#define CHUNK 1024               // elements per sorter CTA

typedef unsigned long long u64;

// scratch (device globals; g_sum_tmp re-zeroed by kernel A every launch,
// everything else fully overwritten -> graph replays are deterministic)
__device__ u64    g_keys[BATCH * NTOK];      // 2 MB, chunk-sorted descending
__device__ int    g_sorted_idx[BATCH * NTOK];
__device__ float  g_tailw[BATCH * TAIL];     // UN-normalized exp weights
__device__ float  g_sum_tmp[BATCH];          // tail softmax denominator

// ---------------------------------------------------------------------------
// helpers
// ---------------------------------------------------------------------------
__device__ __forceinline__ float decode_score(u64 kk) {
    unsigned u = (unsigned)(kk >> 32);
    return (u & 0x80000000u) ? __uint_as_float(u & 0x7FFFFFFFu)
                             : __uint_as_float(~u);
}

__device__ __forceinline__ void cmpswap(u64& a, u64& c, bool desc) {
    bool sw = desc ? (a < c) : (a > c);
    if (sw) { u64 t = a; a = c; c = t; }
}

// warp finish: levels jstart..2 via shfl (2 elems/thread layout), then j=1.
__device__ __forceinline__ void wfin2d(u64& r0, u64& r1,
                                       int base, int jstart, bool d) {
    for (int j = jstart; j >= 2; j >>= 1) {
        int L = j >> 1;
        bool keepmax = (((base & j) == 0) == d);
        u64 o0 = __shfl_xor_sync(0xFFFFFFFFu, r0, L);
        u64 o1 = __shfl_xor_sync(0xFFFFFFFFu, r1, L);
        r0 = keepmax ? (r0 > o0 ? r0 : o0) : (r0 < o0 ? r0 : o0);
        r1 = keepmax ? (r1 > o1 ? r1 : o1) : (r1 < o1 ? r1 : o1);
    }
    cmpswap(r0, r1, d);
}

// ---------------------------------------------------------------------------
// Kernel A: 4 CTAs/batch, 512 threads, 2 elems/thread: sort each 1024-chunk
// DESCENDING. Also zeroes the extra slice and the per-batch softmax sum.
// ---------------------------------------------------------------------------
__global__ __launch_bounds__(512)
void ts_sort1_kernel(const float* __restrict__ ax,
                     const float* __restrict__ ay,
                     float* __restrict__ extra)
{
    __shared__ u64 key[CHUNK];   // 8 KB

    const int chunk = blockIdx.x;        // 0..255
    const int b     = chunk >> 2;
    const int c     = chunk & 3;
    const int tid   = threadIdx.x;
    const int base  = tid << 1;          // element e0 in chunk
    const int gbase = (c << 10) + base;  // token index within batch

    if (tid < 128) extra[b * CH + (c << 7) + tid] = 0.0f;
    if (tid == 0 && c == 0) g_sum_tmp[b] = 0.0f;

    u64 r0, r1;
    {
        float2 x = *(const float2*)(ax + b * NTOK + gbase);
        float2 y = *(const float2*)(ay + b * NTOK + gbase);
        float s0 = x.x + y.x, s1 = x.y + y.y;
        unsigned u0 = __float_as_uint(s0);
        u0 = (u0 & 0x80000000u) ? ~u0 : (u0 | 0x80000000u);
        unsigned u1 = __float_as_uint(s1);
        u1 = (u1 & 0x80000000u) ? ~u1 : (u1 | 0x80000000u);
        r0 = ((u64)u0 << 32) | (unsigned)(~gbase);
        r1 = ((u64)u1 << 32) | (unsigned)(~(gbase + 1));
    }

    // k = 2..64 : registers + shuffles only (descending network)
    cmpswap(r0, r1, (base & 2) == 0);
    for (int k = 4; k <= 64; k <<= 1)
        wfin2d(r0, r1, base, k >> 1, ((base & k) == 0));

    // k = 128..1024 : smem quad passes (levels j,j/2 together), warp finish
    for (int k = 128; k <= CHUNK; k <<= 1) {
        *(ulonglong2*)&key[base] = make_ulonglong2(r0, r1);
        __syncthreads();
        int j = k >> 1;
        while (j >= 64) {
            int j2 = j >> 1;
            if (tid < 256) {
                int q = tid;
                int i = ((q & ~(j2 - 1)) << 2) | (q & (j2 - 1));
                bool d = ((i & k) == 0);
                u64 a0 = key[i];
                u64 a1 = key[i + j2];
                u64 a2 = key[i + 2 * j2];
                u64 a3 = key[i + 3 * j2];
                cmpswap(a0, a2, d);
                cmpswap(a1, a3, d);
                cmpswap(a0, a1, d);
                cmpswap(a2, a3, d);
                key[i]          = a0;
                key[i + j2]     = a1;
                key[i + 2 * j2] = a2;
                key[i + 3 * j2] = a3;
            }
            __syncthreads();
            j >>= 2;
        }
        ulonglong2 p = *(ulonglong2*)&key[base];
        r0 = p.x; r1 = p.y;
        wfin2d(r0, r1, base, j, ((base & k) == 0));   // j is 32 or 16 here
    }

    *(ulonglong2*)(g_keys + b * NTOK + gbase) = make_ulonglong2(r0, r1);

    // all of this CTA's global writes are issued -> allow dependent launch
    cudaTriggerProgrammaticLaunchCompletion();
}

// ---------------------------------------------------------------------------
// Kernel B: merge-by-rank (11-step guarded binary searches). PDL consumer of
// kernel A and PDL producer for the main kernel.
// ---------------------------------------------------------------------------
__global__ __launch_bounds__(512)
void ts_merge_kernel(float* __restrict__ mask_out)
{
    __shared__ u64 D[NTOK];      // 32 KB
    __shared__ float red[16];

    const int cta = blockIdx.x;          // 0..255
    const int b   = cta >> 2;
    const int c   = cta & 3;
    const int tid = threadIdx.x;

    // wait for kernel A's writes (g_keys, g_sum_tmp zero) to be visible
    cudaGridDependencySynchronize();

    // load the whole batch's keys (vectorized, 4 iters of ulonglong2)
    {
        const ulonglong2* src = (const ulonglong2*)(g_keys + b * NTOK);
        ulonglong2* dst = (ulonglong2*)D;
        #pragma unroll
        for (int i = 0; i < 4; ++i)
            dst[tid + (i << 9)] = src[tid + (i << 9)];
    }
    __syncthreads();

    float lsum = 0.0f;

    #pragma unroll
    for (int m = 0; m < 2; ++m) {
        const int pos = (tid << 1) + m;          // position in own chunk
        const u64 e = D[(c << 10) + pos];

        int rank = pos;
        #pragma unroll
        for (int oc = 0; oc < 4; ++oc) {
            if (oc == c) continue;
            const u64* __restrict__ A = D + (oc << 10);
            int lo = 0, hi = CHUNK;
            #pragma unroll
            for (int it = 0; it < 11; ++it) {    // 11 steps for 1025 outcomes
                if (lo < hi) {
                    int mid = (lo + hi) >> 1;
                    if (A[mid] > e) lo = mid + 1; else hi = mid;
                }
            }
            rank += lo;                          // # elements > e in A
        }

        const int idx = (int)(~(unsigned)e);
        g_sorted_idx[b * NTOK + rank] = idx;
        mask_out[b * NTOK + idx] = (rank < NUM_KEEP) ? 1.0f : 0.0f;
        if (rank >= NUM_KEEP) {
            float w = expf(decode_score(e));     // unnormalized; fp32-safe
            g_tailw[b * TAIL + (rank - NUM_KEEP)] = w;
            lsum += w;
        }
    }

    // block-reduce lsum, one atomicAdd per CTA into the batch denominator
    for (int off = 16; off > 0; off >>= 1)
        lsum += __shfl_down_sync(0xFFFFFFFFu, lsum, off);
    if ((tid & 31) == 0) red[tid >> 5] = lsum;
    __syncthreads();
    if (tid < 16) {
        float v = red[tid];
        for (int off = 8; off > 0; off >>= 1)
            v += __shfl_down_sync(0x0000FFFFu, v, off);
        if (tid == 0) atomicAdd(&g_sum_tmp[b], v);
    }

    // all global writes issued -> allow main kernel to proceed
    cudaTriggerProgrammaticLaunchCompletion();
}

// ---------------------------------------------------------------------------
// MAIN kernel: tail accumulation + gather copy. __launch_bounds__(512,4)
// caps regs at 32 -> 4 CTAs/SM; tail path pre-reduces its 4 sub-groups in
// smem before atomics. Copy path computes index arithmetic BEFORE the PDL
// sync so it overlaps the merge kernel's tail.
// ---------------------------------------------------------------------------
__global__ __launch_bounds__(512, 4)
void ts_main_kernel(const float* __restrict__ tokens,
                    float* __restrict__ sel,
                    float* __restrict__ extra)
{
    __shared__ float4 part[3][128];   // 6 KB, tail path only

    if (blockIdx.x < TAIL_CTAS) {
        const int b    = blockIdx.x >> 3;
        const int sub  = threadIdx.x >> 7;                   // 0..3
        const int g    = ((blockIdx.x & 7) << 2) | sub;      // 0..31
        const int lane = threadIdx.x & 127;

        const int* __restrict__ sidx = g_sorted_idx + b * NTOK + NUM_KEEP;
        const float* __restrict__ w  = g_tailw + b * TAIL;
        const float4* __restrict__ tok4 = (const float4*)tokens
                                          + ((long long)b * NTOK << 7);

        cudaGridDependencySynchronize();   // wait for merge results

        float4 acc = make_float4(0.f, 0.f, 0.f, 0.f);
        int r = g;
        for (; r + NGROUP < TAIL; r += 2 * NGROUP) {
            int   i0 = sidx[r],    i1 = sidx[r + NGROUP];
            float w0 = w[r],       w1 = w[r + NGROUP];
            float4 v0 = __ldcs(&tok4[((long long)i0 << 7) + lane]);
            float4 v1 = __ldcs(&tok4[((long long)i1 << 7) + lane]);
            acc.x += w0 * v0.x + w1 * v1.x;
            acc.y += w0 * v0.y + w1 * v1.y;
            acc.z += w0 * v0.z + w1 * v1.z;
            acc.w += w0 * v0.w + w1 * v1.w;
        }
        if (r < TAIL) {
            int i0 = sidx[r];
            float w0 = w[r];
            float4 v0 = __ldcs(&tok4[((long long)i0 << 7) + lane]);
            acc.x += w0 * v0.x; acc.y += w0 * v0.y;
            acc.z += w0 * v0.z; acc.w += w0 * v0.w;
        }

        // intra-CTA reduction: sub-groups 1..3 -> smem, sub-group 0 finishes
        if (sub > 0) part[sub - 1][lane] = acc;
        __syncthreads();
        if (sub == 0) {
            #pragma unroll
            for (int i = 0; i < 3; ++i) {
                float4 p = part[i][lane];
                acc.x += p.x; acc.y += p.y; acc.z += p.z; acc.w += p.w;
            }
            float s = 1.0f / g_sum_tmp[b];
            float* dst = extra + b * CH + (lane << 2);
            atomicAdd(dst + 0, acc.x * s);
            atomicAdd(dst + 1, acc.y * s);
            atomicAdd(dst + 2, acc.z * s);
            atomicAdd(dst + 3, acc.w * s);
        }
    } else {
        const int cta = blockIdx.x - TAIL_CTAS;
        const int v0  = (cta << 12) + threadIdx.x;

        // index arithmetic prelude (independent of merge output)
        int rowoff[8], lanes[8];
        #pragma unroll
        for (int i = 0; i < 8; ++i) {
            int v = v0 + (i << 9);
            int row = v >> 7;                  // b*NUM_KEEP + r
            int b = row / NUM_KEEP;
            int r = row - b * NUM_KEEP;
            rowoff[i] = b * NTOK + r;          // g_sorted_idx offset
            lanes[i]  = (b << 19) | (v & 127); // pack b (for src) + lane
        }

        cudaGridDependencySynchronize();   // wait for merge results

        // two halves of 4 float4s: lower live-register footprint (32-reg cap)
        #pragma unroll
        for (int h = 0; h < 2; ++h) {
            long long srcoff[4];
            #pragma unroll
            for (int i = 0; i < 4; ++i) {
                int q = h * 4 + i;
                int idx = __ldg(&g_sorted_idx[rowoff[q]]);
                int b = lanes[q] >> 19;
                int lane = lanes[q] & 127;
                srcoff[i] = (((long long)b * NTOK + idx) << 7) + lane;
            }
            float4 val[4];
            #pragma unroll
            for (int i = 0; i < 4; ++i)
                val[i] = __ldcs(((const float4*)tokens) + srcoff[i]);
            #pragma unroll
            for (int i = 0; i < 4; ++i)
                __stcs(((float4*)sel) + v0 + ((h * 4 + i) << 9), val[i]);
        }
    }
}

// ---------------------------------------------------------------------------
extern "C" void kernel_launch(void* const* d_in, const int* in_sizes, int n_in,
                              void* d_out, int out_size)
{
    const float* tokens = (const float*)d_in[0];
    const float* ax     = (const float*)d_in[1];
    const float* ay     = (const float*)d_in[2];

    float* out = (float*)d_out;
    float* sel   = out;                                      // B*NUM_KEEP*C
    float* extra = out + (long long)BATCH * NUM_KEEP * CH;   // B*C
    float* mask  = extra + (long long)BATCH * CH;            // B*N

    // kernel A: plain launch
    ts_sort1_kernel<<<BATCH * 4, 512>>>(ax, ay, extra);

    // kernel B and MAIN: programmatic dependent launches
    cudaLaunchAttribute attr[1];
    attr[0].id = cudaLaunchAttributeProgrammaticStreamSerialization;
    attr[0].val.programmaticStreamSerializationAllowed = 1;

    {
        cudaLaunchConfig_t cfg = {};
        cfg.gridDim  = dim3(BATCH * 4);
        cfg.blockDim = dim3(512);
        cfg.attrs = attr;
        cfg.numAttrs = 1;
        cudaLaunchKernelEx(&cfg, ts_merge_kernel, mask);
    }
    {
        cudaLaunchConfig_t cfg = {};
        cfg.gridDim  = dim3(TAIL_CTAS + COPY_CTAS);
        cfg.blockDim = dim3(512);
        cfg.attrs = attr;
        cfg.numAttrs = 1;
        cudaLaunchKernelEx(&cfg, ts_main_kernel, tokens, sel, extra);
    }
}

// round 16
// speedup vs baseline: 1.1386x; 1.0216x over previous
#include <cuda_runtime.h>
#include <cuda_bf16.h>

#define BATCH 64
#define NTOK  4096
#define CH    512
#define NUM_KEEP 2458            // ceil(4096 * 0.6)
#define TAIL (NTOK - NUM_KEEP)   // 1638
#define C4   (CH / 4)            // 128 float4 per token row
#define NGROUP 32                // tail groups per batch
#define TAIL_CTAS (BATCH * 8)    // 512 CTAs, 4 groups of 128 lanes each
#define COPY_CTAS 9832           // sel float4s / 2048 per CTA, exact
#define CHUNK 1024               // elements per sorter CTA

typedef unsigned long long u64;

// scratch (device globals; g_sum_tmp re-zeroed by kernel A every launch,
// everything else fully overwritten -> graph replays are deterministic)
__device__ u64    g_keys[BATCH * NTOK];      // 2 MB, chunk-sorted descending
__device__ int    g_sorted_idx[BATCH * NTOK];
__device__ float  g_tailw[BATCH * TAIL];     // UN-normalized exp weights
__device__ float  g_sum_tmp[BATCH];          // tail softmax denominator

// ---------------------------------------------------------------------------
// helpers
// ---------------------------------------------------------------------------
__device__ __forceinline__ float decode_score(u64 kk) {
    unsigned u = (unsigned)(kk >> 32);
    return (u & 0x80000000u) ? __uint_as_float(u & 0x7FFFFFFFu)
                             : __uint_as_float(~u);
}

__device__ __forceinline__ void cmpswap(u64& a, u64& c, bool desc) {
    bool sw = desc ? (a < c) : (a > c);
    if (sw) { u64 t = a; a = c; c = t; }
}

// warp finish: levels jstart..2 via shfl (2 elems/thread layout), then j=1.
__device__ __forceinline__ void wfin2d(u64& r0, u64& r1,
                                       int base, int jstart, bool d) {
    for (int j = jstart; j >= 2; j >>= 1) {
        int L = j >> 1;
        bool keepmax = (((base & j) == 0) == d);
        u64 o0 = __shfl_xor_sync(0xFFFFFFFFu, r0, L);
        u64 o1 = __shfl_xor_sync(0xFFFFFFFFu, r1, L);
        r0 = keepmax ? (r0 > o0 ? r0 : o0) : (r0 < o0 ? r0 : o0);
        r1 = keepmax ? (r1 > o1 ? r1 : o1) : (r1 < o1 ? r1 : o1);
    }
    cmpswap(r0, r1, d);
}

// ---------------------------------------------------------------------------
// Kernel A: 4 CTAs/batch, 512 threads, 2 elems/thread: sort each 1024-chunk
// DESCENDING. Also zeroes the extra slice and the per-batch softmax sum.
// ---------------------------------------------------------------------------
__global__ __launch_bounds__(512)
void ts_sort1_kernel(const float* __restrict__ ax,
                     const float* __restrict__ ay,
                     float* __restrict__ extra)
{
    __shared__ u64 key[CHUNK];   // 8 KB

    const int chunk = blockIdx.x;        // 0..255
    const int b     = chunk >> 2;
    const int c     = chunk & 3;
    const int tid   = threadIdx.x;
    const int base  = tid << 1;          // element e0 in chunk
    const int gbase = (c << 10) + base;  // token index within batch

    if (tid < 128) extra[b * CH + (c << 7) + tid] = 0.0f;
    if (tid == 0 && c == 0) g_sum_tmp[b] = 0.0f;

    u64 r0, r1;
    {
        float2 x = *(const float2*)(ax + b * NTOK + gbase);
        float2 y = *(const float2*)(ay + b * NTOK + gbase);
        float s0 = x.x + y.x, s1 = x.y + y.y;
        unsigned u0 = __float_as_uint(s0);
        u0 = (u0 & 0x80000000u) ? ~u0 : (u0 | 0x80000000u);
        unsigned u1 = __float_as_uint(s1);
        u1 = (u1 & 0x80000000u) ? ~u1 : (u1 | 0x80000000u);
        r0 = ((u64)u0 << 32) | (unsigned)(~gbase);
        r1 = ((u64)u1 << 32) | (unsigned)(~(gbase + 1));
    }

    // k = 2..64 : registers + shuffles only (descending network)
    cmpswap(r0, r1, (base & 2) == 0);
    for (int k = 4; k <= 64; k <<= 1)
        wfin2d(r0, r1, base, k >> 1, ((base & k) == 0));

    // k = 128..1024 : smem quad passes (levels j,j/2 together), warp finish
    for (int k = 128; k <= CHUNK; k <<= 1) {
        *(ulonglong2*)&key[base] = make_ulonglong2(r0, r1);
        __syncthreads();
        int j = k >> 1;
        while (j >= 64) {
            int j2 = j >> 1;
            if (tid < 256) {
                int q = tid;
                int i = ((q & ~(j2 - 1)) << 2) | (q & (j2 - 1));
                bool d = ((i & k) == 0);
                u64 a0 = key[i];
                u64 a1 = key[i + j2];
                u64 a2 = key[i + 2 * j2];
                u64 a3 = key[i + 3 * j2];
                cmpswap(a0, a2, d);
                cmpswap(a1, a3, d);
                cmpswap(a0, a1, d);
                cmpswap(a2, a3, d);
                key[i]          = a0;
                key[i + j2]     = a1;
                key[i + 2 * j2] = a2;
                key[i + 3 * j2] = a3;
            }
            __syncthreads();
            j >>= 2;
        }
        ulonglong2 p = *(ulonglong2*)&key[base];
        r0 = p.x; r1 = p.y;
        wfin2d(r0, r1, base, j, ((base & k) == 0));   // j is 32 or 16 here
    }

    *(ulonglong2*)(g_keys + b * NTOK + gbase) = make_ulonglong2(r0, r1);

    // all of this CTA's global writes are issued -> allow dependent launch
    cudaTriggerProgrammaticLaunchCompletion();
}

// ---------------------------------------------------------------------------
// Kernel B: merge-by-rank (11-step guarded binary searches). PDL consumer of
// kernel A and PDL producer for the main kernel.
// ---------------------------------------------------------------------------
__global__ __launch_bounds__(512)
void ts_merge_kernel(float* __restrict__ mask_out)
{
    __shared__ u64 D[NTOK];      // 32 KB
    __shared__ float red[16];

    const int cta = blockIdx.x;          // 0..255
    const int b   = cta >> 2;
    const int c   = cta & 3;
    const int tid = threadIdx.x;

    // wait for kernel A's writes (g_keys, g_sum_tmp zero) to be visible
    cudaGridDependencySynchronize();

    // load the whole batch's keys (vectorized, 4 iters of ulonglong2)
    {
        const ulonglong2* src = (const ulonglong2*)(g_keys + b * NTOK);
        ulonglong2* dst = (ulonglong2*)D;
        #pragma unroll
        for (int i = 0; i < 4; ++i)
            dst[tid + (i << 9)] = src[tid + (i << 9)];
    }
    __syncthreads();

    float lsum = 0.0f;

    #pragma unroll
    for (int m = 0; m < 2; ++m) {
        const int pos = (tid << 1) + m;          // position in own chunk
        const u64 e = D[(c << 10) + pos];

        int rank = pos;
        #pragma unroll
        for (int oc = 0; oc < 4; ++oc) {
            if (oc == c) continue;
            const u64* __restrict__ A = D + (oc << 10);
            int lo = 0, hi = CHUNK;
            #pragma unroll
            for (int it = 0; it < 11; ++it) {    // 11 steps for 1025 outcomes
                if (lo < hi) {
                    int mid = (lo + hi) >> 1;
                    if (A[mid] > e) lo = mid + 1; else hi = mid;
                }
            }
            rank += lo;                          // # elements > e in A
        }

        const int idx = (int)(~(unsigned)e);
        g_sorted_idx[b * NTOK + rank] = idx;
        mask_out[b * NTOK + idx] = (rank < NUM_KEEP) ? 1.0f : 0.0f;
        if (rank >= NUM_KEEP) {
            float w = expf(decode_score(e));     // unnormalized; fp32-safe
            g_tailw[b * TAIL + (rank - NUM_KEEP)] = w;
            lsum += w;
        }
    }

    // block-reduce lsum, one atomicAdd per CTA into the batch denominator
    for (int off = 16; off > 0; off >>= 1)
        lsum += __shfl_down_sync(0xFFFFFFFFu, lsum, off);
    if ((tid & 31) == 0) red[tid >> 5] = lsum;
    __syncthreads();
    if (tid < 16) {
        float v = red[tid];
        for (int off = 8; off > 0; off >>= 1)
            v += __shfl_down_sync(0x0000FFFFu, v, off);
        if (tid == 0) atomicAdd(&g_sum_tmp[b], v);
    }

    // all global writes issued -> allow main kernel to proceed
    cudaTriggerProgrammaticLaunchCompletion();
}

// ---------------------------------------------------------------------------
// MAIN kernel: tail accumulation + gather copy. Copy CTAs now move 2048
// float4s each (4/thread) -> 10344 total CTAs (~17.5 waves of ~6us CTAs)
// instead of 9.2 waves of 12us CTAs: halves the end-of-kernel drain tail
// where residency (and achieved BW) decays.
// ---------------------------------------------------------------------------
__global__ __launch_bounds__(512, 4)
void ts_main_kernel(const float* __restrict__ tokens,
                    float* __restrict__ sel,
                    float* __restrict__ extra)
{
    __shared__ float4 part[3][128];   // 6 KB, tail path only

    if (blockIdx.x < TAIL_CTAS) {
        const int b    = blockIdx.x >> 3;
        const int sub  = threadIdx.x >> 7;                   // 0..3
        const int g    = ((blockIdx.x & 7) << 2) | sub;      // 0..31
        const int lane = threadIdx.x & 127;

        const int* __restrict__ sidx = g_sorted_idx + b * NTOK + NUM_KEEP;
        const float* __restrict__ w  = g_tailw + b * TAIL;
        const float4* __restrict__ tok4 = (const float4*)tokens
                                          + ((long long)b * NTOK << 7);

        cudaGridDependencySynchronize();   // wait for merge results

        float4 acc = make_float4(0.f, 0.f, 0.f, 0.f);
        int r = g;
        for (; r + NGROUP < TAIL; r += 2 * NGROUP) {
            int   i0 = sidx[r],    i1 = sidx[r + NGROUP];
            float w0 = w[r],       w1 = w[r + NGROUP];
            float4 v0 = __ldcs(&tok4[((long long)i0 << 7) + lane]);
            float4 v1 = __ldcs(&tok4[((long long)i1 << 7) + lane]);
            acc.x += w0 * v0.x + w1 * v1.x;
            acc.y += w0 * v0.y + w1 * v1.y;
            acc.z += w0 * v0.z + w1 * v1.z;
            acc.w += w0 * v0.w + w1 * v1.w;
        }
        if (r < TAIL) {
            int i0 = sidx[r];
            float w0 = w[r];
            float4 v0 = __ldcs(&tok4[((long long)i0 << 7) + lane]);
            acc.x += w0 * v0.x; acc.y += w0 * v0.y;
            acc.z += w0 * v0.z; acc.w += w0 * v0.w;
        }

        // intra-CTA reduction: sub-groups 1..3 -> smem, sub-group 0 finishes
        if (sub > 0) part[sub - 1][lane] = acc;
        __syncthreads();
        if (sub == 0) {
            #pragma unroll
            for (int i = 0; i < 3; ++i) {
                float4 p = part[i][lane];
                acc.x += p.x; acc.y += p.y; acc.z += p.z; acc.w += p.w;
            }
            float s = 1.0f / g_sum_tmp[b];
            float* dst = extra + b * CH + (lane << 2);
            atomicAdd(dst + 0, acc.x * s);
            atomicAdd(dst + 1, acc.y * s);
            atomicAdd(dst + 2, acc.z * s);
            atomicAdd(dst + 3, acc.w * s);
        }
    } else {
        const int cta = blockIdx.x - TAIL_CTAS;
        const int v0  = (cta << 11) + threadIdx.x;   // 2048 f4s per CTA

        // index arithmetic prelude (independent of merge output)
        int rowoff[4], lanes[4];
        #pragma unroll
        for (int i = 0; i < 4; ++i) {
            int v = v0 + (i << 9);
            int row = v >> 7;                  // b*NUM_KEEP + r
            int b = row / NUM_KEEP;
            int r = row - b * NUM_KEEP;
            rowoff[i] = b * NTOK + r;          // g_sorted_idx offset
            lanes[i]  = (b << 19) | (v & 127); // pack b (for src) + lane
        }

        cudaGridDependencySynchronize();   // wait for merge results

        long long srcoff[4];
        #pragma unroll
        for (int i = 0; i < 4; ++i) {
            int idx = __ldg(&g_sorted_idx[rowoff[i]]);
            int b = lanes[i] >> 19;
            int lane = lanes[i] & 127;
            srcoff[i] = (((long long)b * NTOK + idx) << 7) + lane;
        }
        float4 val[4];
        #pragma unroll
        for (int i = 0; i < 4; ++i)
            val[i] = __ldcs(((const float4*)tokens) + srcoff[i]);
        #pragma unroll
        for (int i = 0; i < 4; ++i)
            __stcs(((float4*)sel) + v0 + (i << 9), val[i]);
    }
}

// ---------------------------------------------------------------------------
extern "C" void kernel_launch(void* const* d_in, const int* in_sizes, int n_in,
                              void* d_out, int out_size)
{
    const float* tokens = (const float*)d_in[0];
    const float* ax     = (const float*)d_in[1];
    const float* ay     = (const float*)d_in[2];

    float* out = (float*)d_out;
    float* sel   = out;                                      // B*NUM_KEEP*C
    float* extra = out + (long long)BATCH * NUM_KEEP * CH;   // B*C
    float* mask  = extra + (long long)BATCH * CH;            // B*N

    // kernel A: plain launch
    ts_sort1_kernel<<<BATCH * 4, 512>>>(ax, ay, extra);

    // kernel B and MAIN: programmatic dependent launches
    cudaLaunchAttribute attr[1];
    attr[0].id = cudaLaunchAttributeProgrammaticStreamSerialization;
    attr[0].val.programmaticStreamSerializationAllowed = 1;

    {
        cudaLaunchConfig_t cfg = {};
        cfg.gridDim  = dim3(BATCH * 4);
        cfg.blockDim = dim3(512);
        cfg.attrs = attr;
        cfg.numAttrs = 1;
        cudaLaunchKernelEx(&cfg, ts_merge_kernel, mask);
    }
    {
        cudaLaunchConfig_t cfg = {};
        cfg.gridDim  = dim3(TAIL_CTAS + COPY_CTAS);
        cfg.blockDim = dim3(512);
        cfg.attrs = attr;
        cfg.numAttrs = 1;
        cudaLaunchKernelEx(&cfg, ts_main_kernel, tokens, sel, extra);
    }
}